// round 5
// baseline (speedup 1.0000x reference)
#include <cuda_runtime.h>
#include <cuda_bf16.h>
#include <math.h>
#include <stdint.h>

#define DDIM 256
#define NQMAX 40000

// ---------------- scratch (device globals; zero-initialized) -----------------
__device__ __align__(16) float g_v  [NQMAX * DDIM];   // value projection (fp32, sampled)
__device__ __align__(16) float g_oa [NQMAX * 144];    // offsets+logits
__device__ __align__(16) float g_tmp[NQMAX * DDIM];   // out-proj / W2 result
__device__ __align__(16) float g_y  [NQMAX * DDIM];   // ln1 out (fp32 residual)

// bf16 hi/lo activation buffers
__device__ __align__(16) __nv_bfloat16 g_qh[NQMAX * DDIM], g_ql[NQMAX * DDIM];
__device__ __align__(16) __nv_bfloat16 g_ah[NQMAX * DDIM], g_al[NQMAX * DDIM];  // value input split
__device__ __align__(16) __nv_bfloat16 g_mh[NQMAX * DDIM], g_ml[NQMAX * DDIM];  // msda out split
__device__ __align__(16) __nv_bfloat16 g_yh[NQMAX * DDIM], g_yl[NQMAX * DDIM];  // ln1 out split
__device__ __align__(16) __nv_bfloat16 g_hh[NQMAX * DDIM], g_hl[NQMAX * DDIM];  // gelu hidden split

// transposed + bf16-split weights: [N][K=256] (boa padded to 256 rows, zeros)
__device__ __align__(16) __nv_bfloat16 g_bv_h[DDIM * DDIM], g_bv_l[DDIM * DDIM];
__device__ __align__(16) __nv_bfloat16 g_bo_h[DDIM * DDIM], g_bo_l[DDIM * DDIM];
__device__ __align__(16) __nv_bfloat16 g_b1_h[DDIM * DDIM], g_b1_l[DDIM * DDIM];
__device__ __align__(16) __nv_bfloat16 g_b2_h[DDIM * DDIM], g_b2_l[DDIM * DDIM];
__device__ __align__(16) __nv_bfloat16 g_boa_h[DDIM * DDIM], g_boa_l[DDIM * DDIM];
__device__ __align__(16) float g_boa[144];

// ---------------- helpers ------------------------------------------------------
__device__ __forceinline__ uint32_t smem_u32(const void* p) {
    uint32_t a;
    asm("{ .reg .u64 t; cvta.to.shared.u64 t, %1; cvt.u32.u64 %0, t; }" : "=r"(a) : "l"(p));
    return a;
}
__device__ __forceinline__ uint32_t pack_bf16(__nv_bfloat16 x, __nv_bfloat16 y) {
    __nv_bfloat162 t(x, y);
    return *reinterpret_cast<uint32_t*>(&t);
}
__device__ __forceinline__ float gelu_exact(float x) {
    return 0.5f * x * (1.0f + erff(x * 0.70710678118654752f));
}

#define LDSM4(r, addr) \
    asm volatile("ldmatrix.sync.aligned.m8n8.x4.shared.b16 {%0,%1,%2,%3}, [%4];" \
        : "=r"((r)[0]), "=r"((r)[1]), "=r"((r)[2]), "=r"((r)[3]) : "r"(addr))

#define CP_ASYNC16Z(dst, src, sz) \
    asm volatile("cp.async.ca.shared.global [%0], [%1], 16, %2;" \
                 :: "r"(dst), "l"(src), "r"(sz))
#define CP_COMMIT() asm volatile("cp.async.commit_group;" ::: "memory")
#define CP_WAIT(n)  asm volatile("cp.async.wait_group %0;" :: "n"(n) : "memory")

__device__ __forceinline__ void mma_bf16(float* d, const uint32_t* a,
                                         uint32_t b0, uint32_t b1) {
    asm volatile(
        "mma.sync.aligned.m16n8k16.row.col.f32.bf16.bf16.f32 "
        "{%0,%1,%2,%3}, {%4,%5,%6,%7}, {%8,%9}, {%0,%1,%2,%3};"
        : "+f"(d[0]), "+f"(d[1]), "+f"(d[2]), "+f"(d[3])
        : "r"(a[0]), "r"(a[1]), "r"(a[2]), "r"(a[3]), "r"(b0), "r"(b1));
}

// ---------------- HMMA GEMM v3: all inputs pre-split bf16, cp.async pipeline --
// C = A[M][256] @ B^T + bias.  CTA tile 128x128, 8 warps (4x2), BK=16, 3 stages.
// MODE 0: write fp32 Cf.  MODE 1: gelu, write bf16 Ch/Cl only.
template<int MODE>
__global__ __launch_bounds__(256, 2)
void gemm_cp(const __nv_bfloat16* __restrict__ Ah, const __nv_bfloat16* __restrict__ Al,
             const __nv_bfloat16* __restrict__ Bh, const __nv_bfloat16* __restrict__ Bl,
             const float* __restrict__ bias,
             float* __restrict__ Cf,
             __nv_bfloat16* __restrict__ Ch, __nv_bfloat16* __restrict__ Cl,
             int M, int N) {
    extern __shared__ __align__(128) char smem[];
    const uint32_t sb = smem_u32(smem);
    const int tid = threadIdx.x;
    const int wid = tid >> 5;
    const int lane = tid & 31;
    const int m0 = blockIdx.y * 128;
    const int n0 = blockIdx.x * 128;
    const int wr = wid & 3;
    const int wc = wid >> 2;

    constexpr int RB = 48;            // smem row bytes (32 data + 16 pad)
    constexpr int STG = 128 * RB;     // 6144 per array
    constexpr int SSTR = 4 * STG;     // 24576 per stage

    const int row = tid >> 1;         // 0..127
    const int half = tid & 1;         // 16B half of 32B chunk
    const uint32_t dstOff = row * RB + half * 16;
    const uint32_t aValid = (m0 + row < M) ? 16u : 0u;
    const __nv_bfloat16* aSrcH = Ah + (size_t)(m0 + row) * DDIM + half * 8;
    const __nv_bfloat16* aSrcL = Al + (size_t)(m0 + row) * DDIM + half * 8;
    const __nv_bfloat16* bSrcH = Bh + (size_t)(n0 + row) * DDIM + half * 8;
    const __nv_bfloat16* bSrcL = Bl + (size_t)(n0 + row) * DDIM + half * 8;

#define ISSUE(c, s) do { \
    const uint32_t base = sb + (s) * SSTR + dstOff; \
    CP_ASYNC16Z(base,             aSrcH + (c) * 16, aValid); \
    CP_ASYNC16Z(base + STG,       aSrcL + (c) * 16, aValid); \
    CP_ASYNC16Z(base + 2 * STG,   bSrcH + (c) * 16, 16u); \
    CP_ASYNC16Z(base + 3 * STG,   bSrcL + (c) * 16, 16u); \
    CP_COMMIT(); } while (0)

    float acc[2][8][4];
#pragma unroll
    for (int i = 0; i < 2; ++i)
#pragma unroll
        for (int j = 0; j < 8; ++j)
#pragma unroll
            for (int k = 0; k < 4; ++k) acc[i][j][k] = 0.f;

    ISSUE(0, 0);
    ISSUE(1, 1);
    ISSUE(2, 2);

    const uint32_t lmA = (wr * 32 + (lane & 15)) * RB + (lane >> 4) * 16;
    const uint32_t lmB = (wc * 64 + (lane & 15)) * RB + (lane >> 4) * 16;

    for (int c = 0; c < 16; ++c) {
        const int s = c % 3;
        const uint32_t stg = sb + s * SSTR;
        CP_WAIT(2);
        __syncthreads();

        uint32_t ah[2][4], al[2][4];
#pragma unroll
        for (int mr = 0; mr < 2; ++mr) {
            LDSM4(ah[mr], stg + lmA + mr * 16 * RB);
            LDSM4(al[mr], stg + STG + lmA + mr * 16 * RB);
        }
#pragma unroll
        for (int nb = 0; nb < 4; ++nb) {
            uint32_t bh[4], bl[4];
            LDSM4(bh, stg + 2 * STG + lmB + nb * 16 * RB);
            LDSM4(bl, stg + 3 * STG + lmB + nb * 16 * RB);
#pragma unroll
            for (int mr = 0; mr < 2; ++mr) {
                mma_bf16(acc[mr][nb * 2 + 0], ah[mr], bh[0], bh[2]);
                mma_bf16(acc[mr][nb * 2 + 1], ah[mr], bh[1], bh[3]);
                mma_bf16(acc[mr][nb * 2 + 0], ah[mr], bl[0], bl[2]);
                mma_bf16(acc[mr][nb * 2 + 1], ah[mr], bl[1], bl[3]);
                mma_bf16(acc[mr][nb * 2 + 0], al[mr], bh[0], bh[2]);
                mma_bf16(acc[mr][nb * 2 + 1], al[mr], bh[1], bh[3]);
            }
        }
        __syncthreads();
        if (c + 3 < 16) ISSUE(c + 3, s);
    }

    // ---- epilogue ----
#pragma unroll
    for (int mr = 0; mr < 2; ++mr) {
        const int r0 = m0 + wr * 32 + mr * 16 + (lane >> 2);
#pragma unroll
        for (int f = 0; f < 8; ++f) {
            const int col = n0 + wc * 64 + f * 8 + (lane & 3) * 2;
            if (col >= N) continue;
            const float b0 = bias[col], b1 = bias[col + 1];
#pragma unroll
            for (int h = 0; h < 2; ++h) {
                const int r = r0 + h * 8;
                if (r >= M) continue;
                float x0 = acc[mr][f][h * 2 + 0] + b0;
                float x1 = acc[mr][f][h * 2 + 1] + b1;
                if (MODE == 1) {
                    x0 = gelu_exact(x0); x1 = gelu_exact(x1);
                    const __nv_bfloat16 h0 = __float2bfloat16(x0);
                    const __nv_bfloat16 h1 = __float2bfloat16(x1);
                    const uint32_t hv = pack_bf16(h0, h1);
                    const uint32_t lv = pack_bf16(
                        __float2bfloat16(x0 - __bfloat162float(h0)),
                        __float2bfloat16(x1 - __bfloat162float(h1)));
                    *reinterpret_cast<uint32_t*>(Ch + (size_t)r * DDIM + col) = hv;
                    *reinterpret_cast<uint32_t*>(Cl + (size_t)r * DDIM + col) = lv;
                } else {
                    *reinterpret_cast<float2*>(Cf + (size_t)r * N + col) = make_float2(x0, x1);
                }
            }
        }
    }
#undef ISSUE
}

// ---------------- split fp32 activations -> bf16 hi/lo -------------------------
__global__ __launch_bounds__(256)
void split_act(const float* __restrict__ x, __nv_bfloat16* __restrict__ h,
               __nv_bfloat16* __restrict__ l, int n4) {
    const int i = blockIdx.x * 256 + threadIdx.x;
    if (i >= n4) return;
    const float4 v = __ldg(reinterpret_cast<const float4*>(x) + i);
    const __nv_bfloat16 h0 = __float2bfloat16(v.x);
    const __nv_bfloat16 h1 = __float2bfloat16(v.y);
    const __nv_bfloat16 h2 = __float2bfloat16(v.z);
    const __nv_bfloat16 h3 = __float2bfloat16(v.w);
    uint2 hv = make_uint2(pack_bf16(h0, h1), pack_bf16(h2, h3));
    uint2 lv = make_uint2(
        pack_bf16(__float2bfloat16(v.x - __bfloat162float(h0)),
                  __float2bfloat16(v.y - __bfloat162float(h1))),
        pack_bf16(__float2bfloat16(v.z - __bfloat162float(h2)),
                  __float2bfloat16(v.w - __bfloat162float(h3))));
    *reinterpret_cast<uint2*>(h + (size_t)i * 4) = hv;
    *reinterpret_cast<uint2*>(l + (size_t)i * 4) = lv;
}

// ---------------- weight transpose + bf16 split --------------------------------
__global__ __launch_bounds__(256)
void convert_weights(const float* __restrict__ Wv, const float* __restrict__ Wo,
                     const float* __restrict__ W1, const float* __restrict__ W2,
                     const float* __restrict__ Woff, const float* __restrict__ Wattn,
                     const float* __restrict__ boff, const float* __restrict__ battn) {
    const int b = blockIdx.x;
    const int k = threadIdx.x;
    if (b == 1168) {
        if (k < 96) g_boa[k] = boff[k];
        else if (k < 144) g_boa[k] = battn[k - 96];
        return;
    }
    const float* W; __nv_bfloat16* oh; __nv_bfloat16* ol; int n, nout, N;
    if (b < 256)       { W = Wv; oh = g_bv_h; ol = g_bv_l; n = b;        nout = n; N = 256; }
    else if (b < 512)  { W = Wo; oh = g_bo_h; ol = g_bo_l; n = b - 256;  nout = n; N = 256; }
    else if (b < 768)  { W = W1; oh = g_b1_h; ol = g_b1_l; n = b - 512;  nout = n; N = 256; }
    else if (b < 1024) { W = W2; oh = g_b2_h; ol = g_b2_l; n = b - 768;  nout = n; N = 256; }
    else {
        nout = b - 1024;
        oh = g_boa_h; ol = g_boa_l;
        if (nout < 96) { W = Woff;  n = nout;      N = 96; }
        else           { W = Wattn; n = nout - 96; N = 48; }
    }
    const float x = W[(size_t)k * N + n];
    const __nv_bfloat16 h = __float2bfloat16(x);
    const __nv_bfloat16 l = __float2bfloat16(x - __bfloat162float(h));
    oh[(size_t)nout * DDIM + k] = h;
    ol[(size_t)nout * DDIM + k] = l;
}

// ---------------- MSDA sampling: corner-parallel, writes bf16 hi/lo ------------
__global__ __launch_bounds__(256)
void msda_sample_kernel(const float* __restrict__ oa, const float* __restrict__ v,
                        const float* __restrict__ ref, const int* __restrict__ ss,
                        __nv_bfloat16* __restrict__ oh, __nv_bfloat16* __restrict__ ol) {
    const int q = blockIdx.x;
    const int h = threadIdx.x >> 5;
    const int lane = threadIdx.x & 31;
    const int corner = lane >> 3;
    const int dx = corner & 1;
    const int dy = corner >> 1;
    const int cg = lane & 7;

    const int H = ss[0];
    const int W = ss[1];

    const float bx = __ldg(ref + q * 2 + 0) * (float)W - 0.5f;
    const float by = __ldg(ref + q * 2 + 1) * (float)H - 0.5f;

    const float* qa = oa + (size_t)q * 144;
    float lg[6];
    float mx = -1e30f;
#pragma unroll
    for (int p = 0; p < 6; ++p) {
        lg[p] = __ldg(qa + 96 + h * 6 + p);
        mx = fmaxf(mx, lg[p]);
    }
    float s = 0.f;
#pragma unroll
    for (int p = 0; p < 6; ++p) { lg[p] = __expf(lg[p] - mx); s += lg[p]; }
    const float inv = 1.f / s;

    const float4* vh = reinterpret_cast<const float4*>(v) + h * 8 + cg;
    float4 acc = make_float4(0.f, 0.f, 0.f, 0.f);

#pragma unroll
    for (int p = 0; p < 6; ++p) {
        const float ox = __ldg(qa + h * 12 + p * 2 + 0);
        const float oy = __ldg(qa + h * 12 + p * 2 + 1);
        const float lx = bx + ox;
        const float ly = by + oy;
        const float x0f = floorf(lx);
        const float y0f = floorf(ly);
        const float fx = lx - x0f;
        const float fy = ly - y0f;
        const int xi = (int)x0f + dx;
        const int yi = (int)y0f + dy;
        const float wx = dx ? fx : 1.f - fx;
        const float wy = dy ? fy : 1.f - fy;
        const bool valid = (xi >= 0) & (xi < W) & (yi >= 0) & (yi < H);
        const float w = valid ? (lg[p] * inv) * wx * wy : 0.f;
        const int xc = min(max(xi, 0), W - 1);
        const int yc = min(max(yi, 0), H - 1);
        const float4 val = __ldg(vh + (size_t)(yc * W + xc) * 64);
        acc.x += w * val.x;
        acc.y += w * val.y;
        acc.z += w * val.z;
        acc.w += w * val.w;
    }

#pragma unroll
    for (int o = 8; o <= 16; o <<= 1) {
        acc.x += __shfl_xor_sync(0xffffffffu, acc.x, o);
        acc.y += __shfl_xor_sync(0xffffffffu, acc.y, o);
        acc.z += __shfl_xor_sync(0xffffffffu, acc.z, o);
        acc.w += __shfl_xor_sync(0xffffffffu, acc.w, o);
    }
    if (lane < 8) {
        const __nv_bfloat16 h0 = __float2bfloat16(acc.x);
        const __nv_bfloat16 h1 = __float2bfloat16(acc.y);
        const __nv_bfloat16 h2 = __float2bfloat16(acc.z);
        const __nv_bfloat16 h3 = __float2bfloat16(acc.w);
        uint2 hv = make_uint2(pack_bf16(h0, h1), pack_bf16(h2, h3));
        uint2 lv = make_uint2(
            pack_bf16(__float2bfloat16(acc.x - __bfloat162float(h0)),
                      __float2bfloat16(acc.y - __bfloat162float(h1))),
            pack_bf16(__float2bfloat16(acc.z - __bfloat162float(h2)),
                      __float2bfloat16(acc.w - __bfloat162float(h3))));
        const size_t o0 = (size_t)q * DDIM + h * 32 + cg * 4;
        *reinterpret_cast<uint2*>(oh + o0) = hv;
        *reinterpret_cast<uint2*>(ol + o0) = lv;
    }
}

// ---------------- fused residual + LayerNorm -----------------------------------
// SPLIT=1: also write bf16 hi/lo of the normalized output.
template<int SPLIT>
__global__ __launch_bounds__(256)
void ln_kernel(const float* __restrict__ x, const float* __restrict__ res,
               const float* __restrict__ g, const float* __restrict__ b,
               float* __restrict__ out,
               __nv_bfloat16* __restrict__ oh, __nv_bfloat16* __restrict__ ol) {
    const int row = blockIdx.x;
    const int tid = threadIdx.x;
    const float v = x[(size_t)row * DDIM + tid] + res[(size_t)row * DDIM + tid];

    float s = v, s2 = v * v;
#pragma unroll
    for (int o = 16; o; o >>= 1) {
        s  += __shfl_xor_sync(0xffffffffu, s, o);
        s2 += __shfl_xor_sync(0xffffffffu, s2, o);
    }
    __shared__ float sh[16];
    const int w = tid >> 5, lane = tid & 31;
    if (lane == 0) { sh[w] = s; sh[w + 8] = s2; }
    __syncthreads();
    if (tid == 0) {
        float a = 0.f, c = 0.f;
#pragma unroll
        for (int i = 0; i < 8; ++i) { a += sh[i]; c += sh[i + 8]; }
        sh[0] = a; sh[8] = c;
    }
    __syncthreads();
    const float mean = sh[0] * (1.f / 256.f);
    const float var  = sh[8] * (1.f / 256.f) - mean * mean;
    const float rstd = rsqrtf(var + 1e-5f);
    const float o = (v - mean) * rstd * g[tid] + b[tid];
    out[(size_t)row * DDIM + tid] = o;
    if (SPLIT) {
        const __nv_bfloat16 hh = __float2bfloat16(o);
        oh[(size_t)row * DDIM + tid] = hh;
        ol[(size_t)row * DDIM + tid] = __float2bfloat16(o - __bfloat162float(hh));
    }
}

// ---------------- launch --------------------------------------------------------
extern "C" void kernel_launch(void* const* d_in, const int* in_sizes, int n_in,
                              void* d_out, int out_size) {
    const float* query  = (const float*)d_in[0];
    const float* value  = (const float*)d_in[1];
    const float* refp   = (const float*)d_in[2];
    const int*   ss     = (const int*)d_in[3];
    const float* W_off  = (const float*)d_in[5];
    const float* b_off  = (const float*)d_in[6];
    const float* W_attn = (const float*)d_in[7];
    const float* b_attn = (const float*)d_in[8];
    const float* W_val  = (const float*)d_in[9];
    const float* b_val  = (const float*)d_in[10];
    const float* W_out  = (const float*)d_in[11];
    const float* b_out  = (const float*)d_in[12];
    const float* ln1_g  = (const float*)d_in[13];
    const float* ln1_b  = (const float*)d_in[14];
    const float* W1     = (const float*)d_in[15];
    const float* b1     = (const float*)d_in[16];
    const float* W2     = (const float*)d_in[17];
    const float* b2     = (const float*)d_in[18];
    const float* ln2_g  = (const float*)d_in[19];
    const float* ln2_b  = (const float*)d_in[20];
    float* out = (float*)d_out;

    const int M  = in_sizes[0] / DDIM;
    const int Mv = in_sizes[1] / DDIM;

    float *pv, *poa, *ptmp, *py, *pboa;
    __nv_bfloat16 *qh, *ql, *avh, *avl, *mh, *ml, *yh, *yl, *hh, *hl;
    __nv_bfloat16 *bvh, *bvl, *boh, *bol, *b1h, *b1l, *b2h, *b2l, *boah, *boal;
    cudaGetSymbolAddress((void**)&pv,   g_v);
    cudaGetSymbolAddress((void**)&poa,  g_oa);
    cudaGetSymbolAddress((void**)&ptmp, g_tmp);
    cudaGetSymbolAddress((void**)&py,   g_y);
    cudaGetSymbolAddress((void**)&pboa, g_boa);
    cudaGetSymbolAddress((void**)&qh,   g_qh);  cudaGetSymbolAddress((void**)&ql, g_ql);
    cudaGetSymbolAddress((void**)&avh,  g_ah);  cudaGetSymbolAddress((void**)&avl, g_al);
    cudaGetSymbolAddress((void**)&mh,   g_mh);  cudaGetSymbolAddress((void**)&ml, g_ml);
    cudaGetSymbolAddress((void**)&yh,   g_yh);  cudaGetSymbolAddress((void**)&yl, g_yl);
    cudaGetSymbolAddress((void**)&hh,   g_hh);  cudaGetSymbolAddress((void**)&hl, g_hl);
    cudaGetSymbolAddress((void**)&bvh,  g_bv_h); cudaGetSymbolAddress((void**)&bvl, g_bv_l);
    cudaGetSymbolAddress((void**)&boh,  g_bo_h); cudaGetSymbolAddress((void**)&bol, g_bo_l);
    cudaGetSymbolAddress((void**)&b1h,  g_b1_h); cudaGetSymbolAddress((void**)&b1l, g_b1_l);
    cudaGetSymbolAddress((void**)&b2h,  g_b2_h); cudaGetSymbolAddress((void**)&b2l, g_b2_l);
    cudaGetSymbolAddress((void**)&boah, g_boa_h); cudaGetSymbolAddress((void**)&boal, g_boa_l);

    const int SMEM = 3 * 4 * 128 * 48;  // 73728 bytes
    cudaFuncSetAttribute(gemm_cp<0>, cudaFuncAttributeMaxDynamicSharedMemorySize, SMEM);
    cudaFuncSetAttribute(gemm_cp<1>, cudaFuncAttributeMaxDynamicSharedMemorySize, SMEM);

    const int gM  = (M + 127) / 128;
    const int gMv = (Mv + 127) / 128;

    // 0) weight + activation conversion
    convert_weights<<<1169, 256>>>(W_val, W_out, W1, W2, W_off, W_attn, b_off, b_attn);
    split_act<<<(M * 64 + 255) / 256, 256>>>(query, qh, ql, M * 64);
    split_act<<<(Mv * 64 + 255) / 256, 256>>>(value, avh, avl, Mv * 64);
    // 1) value projection
    gemm_cp<0><<<dim3(2, gMv), 256, SMEM>>>(avh, avl, bvh, bvl, b_val, pv, nullptr, nullptr, Mv, DDIM);
    // 2) fused offsets+attn logits GEMM (N=144)
    gemm_cp<0><<<dim3(2, gM), 256, SMEM>>>(qh, ql, boah, boal, pboa, poa, nullptr, nullptr, M, 144);
    // 3) deformable sampling -> bf16 hi/lo
    msda_sample_kernel<<<M, 256>>>(poa, pv, refp, ss, mh, ml);
    // 4) output projection + residual + LN1 (ln1 emits fp32 + split)
    gemm_cp<0><<<dim3(2, gM), 256, SMEM>>>(mh, ml, boh, bol, b_out, ptmp, nullptr, nullptr, M, DDIM);
    ln_kernel<1><<<M, 256>>>(ptmp, query, ln1_g, ln1_b, py, yh, yl);
    // 5) FFN
    gemm_cp<1><<<dim3(2, gM), 256, SMEM>>>(yh, yl, b1h, b1l, b1, nullptr, hh, hl, M, DDIM);
    gemm_cp<0><<<dim3(2, gM), 256, SMEM>>>(hh, hl, b2h, b2l, b2, ptmp, nullptr, nullptr, M, DDIM);
    ln_kernel<0><<<M, 256>>>(ptmp, py, ln2_g, ln2_b, out, nullptr, nullptr);
}